// round 16
// baseline (speedup 1.0000x reference)
#include <cuda_runtime.h>
#include <cuda_fp16.h>
#include <cstdint>

#define BB 4
#define SENC 2048
#define SDEC 1024
#define DIM 1024
#define NH 16
#define HD 64
#define CS (0.125f * 1.44269504088896f)   // 1/sqrt(64) * log2(e)
#define WSZ (1024 * 512)

// ================= persistent packed-fp16 scratch (uint32 = 2 fp16) =======
__device__ uint32_t g_dec[4096*512];
__device__ uint32_t g_enc[8192*512];      // compacted key order
__device__ uint32_t g_wt[4][1024*512];    // weights fp16, transposed [n][kpair]
__device__ uint32_t g_Q[4096*512];        // CS pre-folded
__device__ uint32_t g_K[8192*512];        // compacted
__device__ uint32_t g_V[8192*512];        // compacted
__device__ uint32_t g_X[4096*512];
__device__ int g_idx[BB * SENC];
__device__ int g_cnt[BB];

// ============================ helpers ============================
__device__ __forceinline__ uint32_t smem_u32(const void* p) {
    uint32_t a;
    asm("{ .reg .u64 t; cvta.to.shared.u64 t, %1; cvt.u32.u64 %0, t; }" : "=r"(a) : "l"(p));
    return a;
}
__device__ __forceinline__ uint32_t packh2(float x, float y) {
    __half a = __float2half_rn(x), b = __float2half_rn(y);
    return (uint32_t)__half_as_ushort(a) | ((uint32_t)__half_as_ushort(b) << 16);
}
__device__ __forceinline__ void mma_f16(float* d, const uint32_t* a, const uint32_t* b) {
    asm volatile("mma.sync.aligned.m16n8k16.row.col.f32.f16.f16.f32 "
        "{%0,%1,%2,%3}, {%4,%5,%6,%7}, {%8,%9}, {%0,%1,%2,%3};"
        : "+f"(d[0]), "+f"(d[1]), "+f"(d[2]), "+f"(d[3])
        : "r"(a[0]), "r"(a[1]), "r"(a[2]), "r"(a[3]), "r"(b[0]), "r"(b[1]));
}
__device__ __forceinline__ void ldmx4(uint32_t* r, uint32_t addr) {
    asm volatile("ldmatrix.sync.aligned.m8n8.x4.shared.b16 {%0,%1,%2,%3}, [%4];"
        : "=r"(r[0]), "=r"(r[1]), "=r"(r[2]), "=r"(r[3]) : "r"(addr));
}
__device__ __forceinline__ void ldmx4_trans(uint32_t* r, uint32_t addr) {
    asm volatile("ldmatrix.sync.aligned.m8n8.x4.trans.shared.b16 {%0,%1,%2,%3}, [%4];"
        : "=r"(r[0]), "=r"(r[1]), "=r"(r[2]), "=r"(r[3]) : "r"(addr));
}
// exp2(u), bias 0; masked keys clamp to 2^-28 -> flushes to 0 in fp16 P.
__device__ __forceinline__ float exp2q(float u) {
    u = fmaxf(u, -28.0f);
    float n = rintf(u);
    float f = u - n;
    float p = 0.0013333558f;
    p = fmaf(p, f, 0.0096181291f);
    p = fmaf(p, f, 0.0555041087f);
    p = fmaf(p, f, 0.2402265070f);
    p = fmaf(p, f, 0.6931471806f);
    p = fmaf(p, f, 1.0f);
    int sb = (__float2int_rn(n) + 127) << 23;
    return p * __int_as_float(sb);
}
#define CP16(dst, src) \
    asm volatile("cp.async.cg.shared.global [%0], [%1], 16;" :: "r"(dst), "l"(src) : "memory")
#define CP_COMMIT() asm volatile("cp.async.commit_group;" ::: "memory")
#define CP_WAIT1()  asm volatile("cp.async.wait_group 1;" ::: "memory")

// ============================ setup kernels ============================
__global__ __launch_bounds__(1024) void scan_mask(const unsigned int* __restrict__ mask)
{
    __shared__ int ps[1024];
    const int b = blockIdx.x, t = threadIdx.x;
    const unsigned int* m = mask + b * SENC;
    g_idx[b * SENC + 2 * t]     = 0;
    g_idx[b * SENC + 2 * t + 1] = 0;
    int f0 = (m[2 * t] == 0u) ? 1 : 0;
    int f1 = (m[2 * t + 1] == 0u) ? 1 : 0;
    ps[t] = f0 + f1;
    __syncthreads();
    for (int d = 1; d < 1024; d <<= 1) {
        int v = ps[t];
        int add = (t >= d) ? ps[t - d] : 0;
        __syncthreads();
        ps[t] = v + add;
        __syncthreads();
    }
    int excl = (t > 0) ? ps[t - 1] : 0;
    if (f0) g_idx[b * SENC + excl] = 2 * t;
    if (f1) g_idx[b * SENC + excl + f0] = 2 * t + 1;
    if (t == 1023) g_cnt[b] = ps[1023];
}

__global__ __launch_bounds__(256) void conv_acts(
    const float* __restrict__ dec, const float* __restrict__ enc,
    uint32_t* __restrict__ D, uint32_t* __restrict__ E)
{
    int i = blockIdx.x * 256 + threadIdx.x;
    const int NDEC = 4096 * 512;
    if (i < NDEC) {
        float2 v = ((const float2*)dec)[i];
        D[i] = packh2(v.x, v.y);
    } else {
        int j = i - NDEC;
        int r = j >> 9, c = j & 511;
        int b = r >> 11, jj = r & 2047;
        int src = b * SENC + g_idx[b * SENC + jj];
        float2 v = ((const float2*)enc)[(size_t)src * 512 + c];
        E[j] = packh2(v.x, v.y);
    }
}

__global__ __launch_bounds__(256) void conv_wt_all(
    const float* __restrict__ W0, const float* __restrict__ W1,
    const float* __restrict__ W2, const float* __restrict__ W3,
    uint32_t* __restrict__ Th)
{
    __shared__ float tile[64][33];
    const float* W = (blockIdx.z == 0) ? W0 : (blockIdx.z == 1) ? W1
                   : (blockIdx.z == 2) ? W2 : W3;
    uint32_t* Thz = Th + (size_t)blockIdx.z * WSZ;
    int k0 = blockIdx.y * 64, n0 = blockIdx.x * 32;
    int tx = threadIdx.x & 31, ty = threadIdx.x >> 5;
    for (int r = ty; r < 64; r += 8)
        tile[r][tx] = W[(size_t)(k0 + r) * 1024 + n0 + tx];
    __syncthreads();
    for (int nn = ty; nn < 32; nn += 8) {
        float a = tile[2 * tx][nn], b = tile[2 * tx + 1][nn];
        Thz[(size_t)(n0 + nn) * 512 + (k0 >> 1) + tx] = packh2(a, b);
    }
}

// ============================ shared GEMM body (1-pass fp16, KB=64) ======
// A single fp16, W single fp16. Row = 32 data u32 + 4 pad = 36 u32 (144B).
// Stage: A@0 (18432B), B@18432B; stage stride 36864B, double buffered.
#define RST 36
#define GST 36864

__device__ __forceinline__ void gemm_body(
    const uint32_t* __restrict__ A, const uint32_t* __restrict__ Wt,
    const float* __restrict__ bias,
    float* __restrict__ Cf, uint32_t* __restrict__ Ch,
    float scale, int bm, int bn, uint32_t* smu)
{
    const uint32_t sb = smem_u32(smu);
    const int t = threadIdx.x, lane = t & 31, wid = t >> 5;
    const int g = lane >> 2, tq = lane & 3;
    const int wm = wid & 1, wn = wid >> 1;

    float acc[4][4][4];
#pragma unroll
    for (int i = 0; i < 4; i++)
#pragma unroll
        for (int j = 0; j < 4; j++)
#pragma unroll
            for (int k = 0; k < 4; k++) acc[i][j][k] = 0.f;

    // load one 128x64 A tile + 128x64 B tile: 2048 16B-chunks / 256 thr = 8
    auto issue = [&](int kb, int st) {
        const uint32_t base = sb + st * GST;
#pragma unroll
        for (int c = 0; c < 8; c++) {
            int tile = c >> 2;                    // 0=A, 1=B
            int chunk = (c & 3) * 256 + t;        // 0..1023
            int row = chunk >> 3, ch = chunk & 7;
            const uint32_t* src = tile ? Wt : A;
            int grow = (tile ? bn : bm) + row;
            CP16(base + (uint32_t)(tile * 18432 + row * 144 + ch * 16),
                 src + (size_t)grow * 512 + (kb >> 1) + ch * 4);
        }
    };

    issue(0, 0);
    CP_COMMIT();

    const uint32_t a_row = (uint32_t)(wm * 64 + (lane & 15));
    const uint32_t a_k8  = (uint32_t)((lane >> 4) * 16);
    const uint32_t bsel  = (uint32_t)(lane >> 3);
    const uint32_t b_row = (uint32_t)(wn * 32 + (bsel >> 1) * 8 + (lane & 7));
    const uint32_t b_k8  = (uint32_t)((bsel & 1) * 16);

    for (int i = 0; i < 16; i++) {
        if (i + 1 < 16) issue((i + 1) * 64, (i + 1) & 1);
        CP_COMMIT();
        CP_WAIT1();
        __syncthreads();

        const uint32_t stb = sb + (i & 1) * GST;

#pragma unroll
        for (int ks = 0; ks < 4; ks++) {
            uint32_t ah[4][4], bh[4][2];
#pragma unroll
            for (int mi = 0; mi < 4; mi++) {
                uint32_t aa = stb + (a_row + mi * 16) * 144 + ks * 32 + a_k8;
                ldmx4(ah[mi], aa);
            }
#pragma unroll
            for (int p = 0; p < 2; p++) {
                uint32_t ba = stb + 18432 + (b_row + p * 16) * 144 + ks * 32 + b_k8;
                uint32_t rh[4];
                ldmx4(rh, ba);
                bh[2 * p][0] = rh[0]; bh[2 * p][1] = rh[1];
                bh[2 * p + 1][0] = rh[2]; bh[2 * p + 1][1] = rh[3];
            }
#pragma unroll
            for (int mi = 0; mi < 4; mi++)
#pragma unroll
                for (int ni = 0; ni < 4; ni++)
                    mma_f16(acc[mi][ni], ah[mi], bh[ni]);
        }
        __syncthreads();
    }

#pragma unroll
    for (int mi = 0; mi < 4; mi++) {
        int r0 = bm + wm * 64 + mi * 16 + g;
#pragma unroll
        for (int ni = 0; ni < 4; ni++) {
            int c = bn + wn * 32 + ni * 8 + 2 * tq;
            float2 bb = *(const float2*)(bias + c);
            float* d = acc[mi][ni];
            if (Cf) {
                *(float2*)(Cf + (size_t)r0 * 1024 + c) =
                    make_float2(d[0] + bb.x, d[1] + bb.y);
                *(float2*)(Cf + (size_t)(r0 + 8) * 1024 + c) =
                    make_float2(d[2] + bb.x, d[3] + bb.y);
            } else {
                float x0 = (d[0] + bb.x) * scale, y0 = (d[1] + bb.y) * scale;
                float x1 = (d[2] + bb.x) * scale, y1 = (d[3] + bb.y) * scale;
                size_t cp = (size_t)(c >> 1);
                Ch[(size_t)r0 * 512 + cp]       = packh2(x0, y0);
                Ch[(size_t)(r0 + 8) * 512 + cp] = packh2(x1, y1);
            }
        }
    }
}

__global__ __launch_bounds__(256) void hgemm_qkv(
    const uint32_t* __restrict__ dec, const uint32_t* __restrict__ enc,
    const uint32_t* __restrict__ wt,
    const float* __restrict__ q_b, const float* __restrict__ k_b,
    const float* __restrict__ v_b,
    uint32_t* __restrict__ Q, uint32_t* __restrict__ K, uint32_t* __restrict__ V)
{
    extern __shared__ uint32_t smu[];
    const int yt = blockIdx.y;
    const int bn = blockIdx.x * 128;
    if (yt < 32) {
        gemm_body(dec, wt, q_b, nullptr, Q, CS, yt * 128, bn, smu);
    } else if (yt < 96) {
        int bm = (yt - 32) * 128;
        int b = bm >> 11;
        if ((bm & 2047) >= ((g_cnt[b] + 127) & ~127)) return;
        gemm_body(enc, wt + WSZ, k_b, nullptr, K, 1.0f, bm, bn, smu);
    } else {
        int bm = (yt - 96) * 128;
        int b = bm >> 11;
        if ((bm & 2047) >= ((g_cnt[b] + 127) & ~127)) return;
        gemm_body(enc, wt + 2 * WSZ, v_b, nullptr, V, 1.0f, bm, bn, smu);
    }
}

__global__ __launch_bounds__(256) void hgemm_o(
    const uint32_t* __restrict__ X, const uint32_t* __restrict__ Wt,
    const float* __restrict__ bias, float* __restrict__ Cf)
{
    extern __shared__ uint32_t smu[];
    gemm_body(X, Wt, bias, Cf, nullptr, 1.0f,
              blockIdx.y * 128, blockIdx.x * 128, smu);
}

// ============================ FA2 attention (128-key tiles) ==============
// QK^T 1-pass, PV 1-pass. Stage: K@0 (18432B), V@18432B; stride 36864B.
#define ATST 36864
#define ATTN_SMEM (2 * ATST)

__global__ __launch_bounds__(128, 2) void attn_mma()
{
    extern __shared__ uint32_t smu[];
    const uint32_t sb = smem_u32(smu);
    const int t = threadIdx.x, w = t >> 5, lane = t & 31;
    const int g = lane >> 2, tq = lane & 3;
    const int qt = blockIdx.x, h = blockIdx.y, b = blockIdx.z;
    const int q0 = qt * 64;
    const int cntb = g_cnt[b];
    const int nt = (cntb + 127) >> 7;

    const size_t qrow = (size_t)(b * SDEC + q0 + 16 * w);
    uint32_t qh[4][4];
#pragma unroll
    for (int ks = 0; ks < 4; ks++) {
        size_t p0 = (qrow + g) * 512 + h * 32 + ks * 8 + tq;
        size_t p1 = (qrow + g + 8) * 512 + h * 32 + ks * 8 + tq;
        qh[ks][0] = g_Q[p0]; qh[ks][1] = g_Q[p1];
        qh[ks][2] = g_Q[p0 + 4]; qh[ks][3] = g_Q[p1 + 4];
    }

    float l0 = 0.f, l1 = 0.f;
    float oacc[8][4];
#pragma unroll
    for (int ni = 0; ni < 8; ni++)
#pragma unroll
        for (int k = 0; k < 4; k++) oacc[ni][k] = 0.f;

    // load 128-key K + V tiles: 2048 chunks / 128 thr = 16 per thread
    auto issue = [&](int kb, int st) {
        const uint32_t base = sb + st * ATST;
        const uint32_t* srcs[2] = {g_K, g_V};
        const int keyl = t >> 3, ch = t & 7;
#pragma unroll
        for (int c = 0; c < 16; c++) {
            int tile = c >> 3;
            int key = (c & 7) * 16 + keyl;
            CP16(base + (uint32_t)(tile * 18432 + key * 144 + ch * 16),
                 srcs[tile] + (size_t)(b * SENC + kb + key) * 512 + h * 32 + ch * 4);
        }
    };

    issue(0, 0);
    CP_COMMIT();

    const uint32_t ksel  = (uint32_t)(lane >> 3);
    const uint32_t k_row = (uint32_t)((ksel >> 1) * 8 + (lane & 7));
    const uint32_t k_k8  = (uint32_t)((ksel & 1) * 16);

    for (int i = 0; i < nt; i++) {
        const int k0 = i * 128, st = i & 1;
        if (i + 1 < nt) issue((i + 1) * 128, (i + 1) & 1);
        CP_COMMIT();
        CP_WAIT1();
        __syncthreads();

        const uint32_t kbase = sb + st * ATST;
        const uint32_t vbase = kbase + 18432;

        float sacc[16][4];
#pragma unroll
        for (int ni = 0; ni < 16; ni++)
#pragma unroll
            for (int k = 0; k < 4; k++) sacc[ni][k] = 0.f;
#pragma unroll
        for (int ks = 0; ks < 4; ks++) {
#pragma unroll
            for (int p = 0; p < 8; p++) {
                uint32_t ka = kbase + (k_row + p * 16) * 144 + ks * 32 + k_k8;
                uint32_t rh[4];
                ldmx4(rh, ka);
                mma_f16(sacc[2 * p],     qh[ks], &rh[0]);
                mma_f16(sacc[2 * p + 1], qh[ks], &rh[2]);
            }
        }

        if (k0 + 128 > cntb) {
#pragma unroll
            for (int ni = 0; ni < 16; ni++) {
                int c0 = k0 + 8 * ni + 2 * tq;
                if (c0 >= cntb)     { sacc[ni][0] = -1e30f; sacc[ni][2] = -1e30f; }
                if (c0 + 1 >= cntb) { sacc[ni][1] = -1e30f; sacc[ni][3] = -1e30f; }
            }
        }

        // fixed-max softmax (bias 0)
        float rs0 = 0.f, rs1 = 0.f;
#pragma unroll
        for (int ni = 0; ni < 16; ni++) {
            sacc[ni][0] = exp2q(sacc[ni][0]); rs0 += sacc[ni][0];
            sacc[ni][1] = exp2q(sacc[ni][1]); rs0 += sacc[ni][1];
            sacc[ni][2] = exp2q(sacc[ni][2]); rs1 += sacc[ni][2];
            sacc[ni][3] = exp2q(sacc[ni][3]); rs1 += sacc[ni][3];
        }
        rs0 += __shfl_xor_sync(0xffffffffu, rs0, 1);
        rs0 += __shfl_xor_sync(0xffffffffu, rs0, 2);
        rs1 += __shfl_xor_sync(0xffffffffu, rs1, 1);
        rs1 += __shfl_xor_sync(0xffffffffu, rs1, 2);
        l0 += rs0;
        l1 += rs1;

        uint32_t pah[8][4];
#pragma unroll
        for (int j = 0; j < 8; j++) {
            pah[j][0] = packh2(sacc[2 * j][0], sacc[2 * j][1]);
            pah[j][1] = packh2(sacc[2 * j][2], sacc[2 * j][3]);
            pah[j][2] = packh2(sacc[2 * j + 1][0], sacc[2 * j + 1][1]);
            pah[j][3] = packh2(sacc[2 * j + 1][2], sacc[2 * j + 1][3]);
        }

        // O += P V : 1 pass over 8 k16 steps
#pragma unroll
        for (int j = 0; j < 8; j++) {
            uint32_t rowoff = (uint32_t)((16 * j + (lane & 15)) * 144);
#pragma unroll
            for (int n2 = 0; n2 < 8; n2 += 2) {
                uint32_t va = vbase + rowoff + n2 * 16 + ((lane >> 4) & 1) * 16;
                uint32_t vrh[4];
                ldmx4_trans(vrh, va);
                mma_f16(oacc[n2],     pah[j], &vrh[0]);
                mma_f16(oacc[n2 + 1], pah[j], &vrh[2]);
            }
        }
        __syncthreads();
    }

    float inv0 = 1.0f / l0, inv1 = 1.0f / l1;
    const size_t row0 = qrow + g;
#pragma unroll
    for (int ni = 0; ni < 8; ni++) {
        size_t cp = (size_t)(h * 32 + ni * 4 + tq);
        float x0 = oacc[ni][0] * inv0, y0 = oacc[ni][1] * inv0;
        float x1 = oacc[ni][2] * inv1, y1 = oacc[ni][3] * inv1;
        g_X[row0 * 512 + cp]       = packh2(x0, y0);
        g_X[(row0 + 8) * 512 + cp] = packh2(x1, y1);
    }
}

// ============================ Launch ============================
extern "C" void kernel_launch(void* const* d_in, const int* in_sizes, int n_in,
                              void* d_out, int out_size)
{
    const float*        enc      = (const float*)d_in[0];
    const unsigned int* enc_mask = (const unsigned int*)d_in[1];
    const float*        dec      = (const float*)d_in[2];
    const float*        q_w      = (const float*)d_in[3];
    const float*        q_b      = (const float*)d_in[4];
    const float*        k_w      = (const float*)d_in[5];
    const float*        k_b      = (const float*)d_in[6];
    const float*        v_w      = (const float*)d_in[7];
    const float*        v_b      = (const float*)d_in[8];
    const float*        o_w      = (const float*)d_in[9];
    const float*        o_b      = (const float*)d_in[10];
    float*              out      = (float*)d_out;

    uint32_t *pdec, *penc, *pwt, *pQ, *pK, *pV, *pX;
    cudaGetSymbolAddress((void**)&pdec, g_dec);
    cudaGetSymbolAddress((void**)&penc, g_enc);
    cudaGetSymbolAddress((void**)&pwt,  g_wt);
    cudaGetSymbolAddress((void**)&pQ,   g_Q);
    cudaGetSymbolAddress((void**)&pK,   g_K);
    cudaGetSymbolAddress((void**)&pV,   g_V);
    cudaGetSymbolAddress((void**)&pX,   g_X);

    cudaFuncSetAttribute(hgemm_qkv, cudaFuncAttributeMaxDynamicSharedMemorySize, 2 * GST);
    cudaFuncSetAttribute(hgemm_o,   cudaFuncAttributeMaxDynamicSharedMemorySize, 2 * GST);
    cudaFuncSetAttribute(attn_mma,  cudaFuncAttributeMaxDynamicSharedMemorySize, ATTN_SMEM);

    conv_wt_all<<<dim3(32, 16, 4), 256>>>(q_w, k_w, v_w, o_w, pwt);
    scan_mask<<<BB, 1024>>>(enc_mask);
    conv_acts<<<(4096 + 8192) * 512 / 256, 256>>>(dec, enc, pdec, penc);

    hgemm_qkv<<<dim3(8, 160), 256, 2 * GST>>>(pdec, penc, pwt,
                                              q_b, k_b, v_b, pQ, pK, pV);

    attn_mma<<<dim3(SDEC / 64, NH, BB), 128, ATTN_SMEM>>>();

    hgemm_o<<<dim3(8, 32), 256, 2 * GST>>>(pX, pwt + 3 * WSZ, o_b, out);
}

// round 17
// speedup vs baseline: 1.2438x; 1.2438x over previous
#include <cuda_runtime.h>
#include <cuda_fp16.h>
#include <cstdint>

#define BB 4
#define SENC 2048
#define SDEC 1024
#define DIM 1024
#define NH 16
#define HD 64
#define CS (0.125f * 1.44269504088896f)   // 1/sqrt(64) * log2(e)
#define WSZ (1024 * 512)

// ================= persistent packed-fp16 scratch (uint32 = 2 fp16) =======
__device__ uint32_t g_dec[4096*512];
__device__ uint32_t g_enc[8192*512];      // compacted key order
__device__ uint32_t g_wt[4][1024*512];    // weights fp16, transposed [n][kpair]
__device__ uint32_t g_Q[4096*512];        // CS pre-folded
__device__ uint32_t g_K[8192*512];        // compacted
__device__ uint32_t g_V[8192*512];        // compacted
__device__ uint32_t g_X[4096*512];
__device__ int g_idx[BB * SENC];
__device__ int g_cnt[BB];

// ============================ helpers ============================
__device__ __forceinline__ uint32_t smem_u32(const void* p) {
    uint32_t a;
    asm("{ .reg .u64 t; cvta.to.shared.u64 t, %1; cvt.u32.u64 %0, t; }" : "=r"(a) : "l"(p));
    return a;
}
__device__ __forceinline__ uint32_t packh2(float x, float y) {
    __half a = __float2half_rn(x), b = __float2half_rn(y);
    return (uint32_t)__half_as_ushort(a) | ((uint32_t)__half_as_ushort(b) << 16);
}
__device__ __forceinline__ void mma_f16(float* d, const uint32_t* a, const uint32_t* b) {
    asm volatile("mma.sync.aligned.m16n8k16.row.col.f32.f16.f16.f32 "
        "{%0,%1,%2,%3}, {%4,%5,%6,%7}, {%8,%9}, {%0,%1,%2,%3};"
        : "+f"(d[0]), "+f"(d[1]), "+f"(d[2]), "+f"(d[3])
        : "r"(a[0]), "r"(a[1]), "r"(a[2]), "r"(a[3]), "r"(b[0]), "r"(b[1]));
}
__device__ __forceinline__ void ldmx4(uint32_t* r, uint32_t addr) {
    asm volatile("ldmatrix.sync.aligned.m8n8.x4.shared.b16 {%0,%1,%2,%3}, [%4];"
        : "=r"(r[0]), "=r"(r[1]), "=r"(r[2]), "=r"(r[3]) : "r"(addr));
}
__device__ __forceinline__ void ldmx4_trans(uint32_t* r, uint32_t addr) {
    asm volatile("ldmatrix.sync.aligned.m8n8.x4.trans.shared.b16 {%0,%1,%2,%3}, [%4];"
        : "=r"(r[0]), "=r"(r[1]), "=r"(r[2]), "=r"(r[3]) : "r"(addr));
}
// exp2(u), bias 0; masked keys clamp to 2^-28 -> flushes to 0 in fp16 P.
__device__ __forceinline__ float exp2q(float u) {
    u = fmaxf(u, -28.0f);
    float n = rintf(u);
    float f = u - n;
    float p = 0.0013333558f;
    p = fmaf(p, f, 0.0096181291f);
    p = fmaf(p, f, 0.0555041087f);
    p = fmaf(p, f, 0.2402265070f);
    p = fmaf(p, f, 0.6931471806f);
    p = fmaf(p, f, 1.0f);
    int sb = (__float2int_rn(n) + 127) << 23;
    return p * __int_as_float(sb);
}
#define CP16(dst, src) \
    asm volatile("cp.async.cg.shared.global [%0], [%1], 16;" :: "r"(dst), "l"(src) : "memory")
#define CP_COMMIT() asm volatile("cp.async.commit_group;" ::: "memory")
#define CP_WAIT1()  asm volatile("cp.async.wait_group 1;" ::: "memory")

// ============================ setup kernels ============================
__global__ __launch_bounds__(1024) void scan_mask(const unsigned int* __restrict__ mask)
{
    __shared__ int ps[1024];
    const int b = blockIdx.x, t = threadIdx.x;
    const unsigned int* m = mask + b * SENC;
    g_idx[b * SENC + 2 * t]     = 0;
    g_idx[b * SENC + 2 * t + 1] = 0;
    int f0 = (m[2 * t] == 0u) ? 1 : 0;
    int f1 = (m[2 * t + 1] == 0u) ? 1 : 0;
    ps[t] = f0 + f1;
    __syncthreads();
    for (int d = 1; d < 1024; d <<= 1) {
        int v = ps[t];
        int add = (t >= d) ? ps[t - d] : 0;
        __syncthreads();
        ps[t] = v + add;
        __syncthreads();
    }
    int excl = (t > 0) ? ps[t - 1] : 0;
    if (f0) g_idx[b * SENC + excl] = 2 * t;
    if (f1) g_idx[b * SENC + excl + f0] = 2 * t + 1;
    if (t == 1023) g_cnt[b] = ps[1023];
}

// float4 per thread: dec covers 4096*512 u32 (i < 2*NDEC4 u32 pairs), enc after.
__global__ __launch_bounds__(256) void conv_acts(
    const float* __restrict__ dec, const float* __restrict__ enc,
    uint32_t* __restrict__ D, uint32_t* __restrict__ E)
{
    int i = blockIdx.x * 256 + threadIdx.x;       // float4 index
    const int NDEC4 = 4096 * 256;                  // dec float4 count
    if (i < NDEC4) {
        float4 v = ((const float4*)dec)[i];
        D[2 * i]     = packh2(v.x, v.y);
        D[2 * i + 1] = packh2(v.z, v.w);
    } else {
        int j = i - NDEC4;                         // enc float4 index
        int r = j >> 8, c = j & 255;               // 256 float4 per row
        int b = r >> 11, jj = r & 2047;
        int src = b * SENC + g_idx[b * SENC + jj];
        float4 v = ((const float4*)enc)[(size_t)src * 256 + c];
        E[2 * j]     = packh2(v.x, v.y);
        E[2 * j + 1] = packh2(v.z, v.w);
    }
}

__global__ __launch_bounds__(256) void conv_wt_all(
    const float* __restrict__ W0, const float* __restrict__ W1,
    const float* __restrict__ W2, const float* __restrict__ W3,
    uint32_t* __restrict__ Th)
{
    __shared__ float tile[64][33];
    const float* W = (blockIdx.z == 0) ? W0 : (blockIdx.z == 1) ? W1
                   : (blockIdx.z == 2) ? W2 : W3;
    uint32_t* Thz = Th + (size_t)blockIdx.z * WSZ;
    int k0 = blockIdx.y * 64, n0 = blockIdx.x * 32;
    int tx = threadIdx.x & 31, ty = threadIdx.x >> 5;
    for (int r = ty; r < 64; r += 8)
        tile[r][tx] = W[(size_t)(k0 + r) * 1024 + n0 + tx];
    __syncthreads();
    for (int nn = ty; nn < 32; nn += 8) {
        float a = tile[2 * tx][nn], b = tile[2 * tx + 1][nn];
        Thz[(size_t)(n0 + nn) * 512 + (k0 >> 1) + tx] = packh2(a, b);
    }
}

// ============================ shared GEMM body (1-pass fp16, KB=32) ======
// A single fp16, W single fp16. Stage: A@0, B@10240B; stride 20480B.
#define AST 20
#define GST 20480

__device__ __forceinline__ void gemm_body(
    const uint32_t* __restrict__ A, const uint32_t* __restrict__ Wt,
    const float* __restrict__ bias,
    float* __restrict__ Cf, uint32_t* __restrict__ Ch,
    float scale, int bm, int bn, uint32_t* smu)
{
    const uint32_t sb = smem_u32(smu);
    const int t = threadIdx.x, lane = t & 31, wid = t >> 5;
    const int g = lane >> 2, tq = lane & 3;
    const int wm = wid & 1, wn = wid >> 1;

    float acc[4][4][4];
#pragma unroll
    for (int i = 0; i < 4; i++)
#pragma unroll
        for (int j = 0; j < 4; j++)
#pragma unroll
            for (int k = 0; k < 4; k++) acc[i][j][k] = 0.f;

    auto issue = [&](int kb, int st) {
        const uint32_t base = sb + st * GST;
        const int row = t >> 2, ch = t & 3;
#pragma unroll
        for (int c = 0; c < 4; c++) {
            int tile = c >> 1;
            int r = (c & 1) * 64 + row;
            const uint32_t* src = (tile == 0) ? A : Wt;
            int grow = ((tile == 0) ? bm : bn) + r;
            CP16(base + (uint32_t)(tile * 2560 + r * AST + ch * 4) * 4,
                 src + (size_t)grow * 512 + (kb >> 1) + ch * 4);
        }
    };

    issue(0, 0);
    CP_COMMIT();

    const uint32_t a_row = (uint32_t)(wm * 64 + (lane & 15));
    const uint32_t a_k8  = (uint32_t)((lane >> 4) * 16);
    const uint32_t bsel  = (uint32_t)(lane >> 3);
    const uint32_t b_row = (uint32_t)(wn * 32 + (bsel >> 1) * 8 + (lane & 7));
    const uint32_t b_k8  = (uint32_t)((bsel & 1) * 16);

    for (int i = 0; i < 32; i++) {
        if (i + 1 < 32) issue((i + 1) * 32, (i + 1) & 1);
        CP_COMMIT();
        CP_WAIT1();
        __syncthreads();

        const uint32_t stb = sb + (i & 1) * GST;

#pragma unroll
        for (int ks = 0; ks < 2; ks++) {
            uint32_t ah[4][4], bh[4][2];
#pragma unroll
            for (int mi = 0; mi < 4; mi++) {
                uint32_t aa = stb + (a_row + mi * 16) * (AST * 4) + ks * 32 + a_k8;
                ldmx4(ah[mi], aa);
            }
#pragma unroll
            for (int p = 0; p < 2; p++) {
                uint32_t ba = stb + 10240 + (b_row + p * 16) * (AST * 4) + ks * 32 + b_k8;
                uint32_t rh[4];
                ldmx4(rh, ba);
                bh[2 * p][0] = rh[0]; bh[2 * p][1] = rh[1];
                bh[2 * p + 1][0] = rh[2]; bh[2 * p + 1][1] = rh[3];
            }
#pragma unroll
            for (int mi = 0; mi < 4; mi++)
#pragma unroll
                for (int ni = 0; ni < 4; ni++)
                    mma_f16(acc[mi][ni], ah[mi], bh[ni]);
        }
        __syncthreads();
    }

#pragma unroll
    for (int mi = 0; mi < 4; mi++) {
        int r0 = bm + wm * 64 + mi * 16 + g;
#pragma unroll
        for (int ni = 0; ni < 4; ni++) {
            int c = bn + wn * 32 + ni * 8 + 2 * tq;
            float2 bb = *(const float2*)(bias + c);
            float* d = acc[mi][ni];
            if (Cf) {
                *(float2*)(Cf + (size_t)r0 * 1024 + c) =
                    make_float2(d[0] + bb.x, d[1] + bb.y);
                *(float2*)(Cf + (size_t)(r0 + 8) * 1024 + c) =
                    make_float2(d[2] + bb.x, d[3] + bb.y);
            } else {
                float x0 = (d[0] + bb.x) * scale, y0 = (d[1] + bb.y) * scale;
                float x1 = (d[2] + bb.x) * scale, y1 = (d[3] + bb.y) * scale;
                size_t cp = (size_t)(c >> 1);
                Ch[(size_t)r0 * 512 + cp]       = packh2(x0, y0);
                Ch[(size_t)(r0 + 8) * 512 + cp] = packh2(x1, y1);
            }
        }
    }
}

__global__ __launch_bounds__(256) void hgemm_qkv(
    const uint32_t* __restrict__ dec, const uint32_t* __restrict__ enc,
    const uint32_t* __restrict__ wt,
    const float* __restrict__ q_b, const float* __restrict__ k_b,
    const float* __restrict__ v_b,
    uint32_t* __restrict__ Q, uint32_t* __restrict__ K, uint32_t* __restrict__ V)
{
    extern __shared__ uint32_t smu[];
    const int yt = blockIdx.y;
    const int bn = blockIdx.x * 128;
    if (yt < 32) {
        gemm_body(dec, wt, q_b, nullptr, Q, CS, yt * 128, bn, smu);
    } else if (yt < 96) {
        int bm = (yt - 32) * 128;
        int b = bm >> 11;
        if ((bm & 2047) >= ((g_cnt[b] + 127) & ~127)) return;
        gemm_body(enc, wt + WSZ, k_b, nullptr, K, 1.0f, bm, bn, smu);
    } else {
        int bm = (yt - 96) * 128;
        int b = bm >> 11;
        if ((bm & 2047) >= ((g_cnt[b] + 127) & ~127)) return;
        gemm_body(enc, wt + 2 * WSZ, v_b, nullptr, V, 1.0f, bm, bn, smu);
    }
}

__global__ __launch_bounds__(256) void hgemm_o(
    const uint32_t* __restrict__ X, const uint32_t* __restrict__ Wt,
    const float* __restrict__ bias, float* __restrict__ Cf)
{
    extern __shared__ uint32_t smu[];
    gemm_body(X, Wt, bias, Cf, nullptr, 1.0f,
              blockIdx.y * 128, blockIdx.x * 128, smu);
}

// ============================ FA2 attention (64-key tiles, 1-pass) =======
#define ATST 18432
#define ATTN_SMEM (2 * ATST)

__global__ __launch_bounds__(128, 2) void attn_mma()
{
    extern __shared__ uint32_t smu[];
    const uint32_t sb = smem_u32(smu);
    const int t = threadIdx.x, w = t >> 5, lane = t & 31;
    const int g = lane >> 2, tq = lane & 3;
    const int qt = blockIdx.x, h = blockIdx.y, b = blockIdx.z;
    const int q0 = qt * 64;
    const int cntb = g_cnt[b];
    const int nt = (cntb + 63) >> 6;

    const size_t qrow = (size_t)(b * SDEC + q0 + 16 * w);
    uint32_t qh[4][4];
#pragma unroll
    for (int ks = 0; ks < 4; ks++) {
        size_t p0 = (qrow + g) * 512 + h * 32 + ks * 8 + tq;
        size_t p1 = (qrow + g + 8) * 512 + h * 32 + ks * 8 + tq;
        qh[ks][0] = g_Q[p0]; qh[ks][1] = g_Q[p1];
        qh[ks][2] = g_Q[p0 + 4]; qh[ks][3] = g_Q[p1 + 4];
    }

    float l0 = 0.f, l1 = 0.f;
    float oacc[8][4];
#pragma unroll
    for (int ni = 0; ni < 8; ni++)
#pragma unroll
        for (int k = 0; k < 4; k++) oacc[ni][k] = 0.f;

    auto issue = [&](int kb, int st) {
        const uint32_t base = sb + st * ATST;
        const uint32_t* srcs[2] = {g_K, g_V};
        const int keyl = t >> 3, ch = t & 7;
#pragma unroll
        for (int c = 0; c < 8; c++) {
            int tile = c >> 2;
            int key = (c & 3) * 16 + keyl;
            CP16(base + (uint32_t)(tile * 9216 + key * 144 + ch * 16),
                 srcs[tile] + (size_t)(b * SENC + kb + key) * 512 + h * 32 + ch * 4);
        }
    };

    issue(0, 0);
    CP_COMMIT();

    const uint32_t ksel  = (uint32_t)(lane >> 3);
    const uint32_t k_row = (uint32_t)((ksel >> 1) * 8 + (lane & 7));
    const uint32_t k_k8  = (uint32_t)((ksel & 1) * 16);

    for (int i = 0; i < nt; i++) {
        const int k0 = i * 64, st = i & 1;
        if (i + 1 < nt) issue((i + 1) * 64, (i + 1) & 1);
        CP_COMMIT();
        CP_WAIT1();
        __syncthreads();

        const uint32_t kbase = sb + st * ATST;
        const uint32_t vbase = kbase + 9216;

        float sacc[8][4];
#pragma unroll
        for (int ni = 0; ni < 8; ni++)
#pragma unroll
            for (int k = 0; k < 4; k++) sacc[ni][k] = 0.f;
#pragma unroll
        for (int ks = 0; ks < 4; ks++) {
#pragma unroll
            for (int p = 0; p < 4; p++) {
                uint32_t ka = kbase + (k_row + p * 16) * 144 + ks * 32 + k_k8;
                uint32_t rh[4];
                ldmx4(rh, ka);
                mma_f16(sacc[2 * p],     qh[ks], &rh[0]);
                mma_f16(sacc[2 * p + 1], qh[ks], &rh[2]);
            }
        }

        if (k0 + 64 > cntb) {
#pragma unroll
            for (int ni = 0; ni < 8; ni++) {
                int c0 = k0 + 8 * ni + 2 * tq;
                if (c0 >= cntb)     { sacc[ni][0] = -1e30f; sacc[ni][2] = -1e30f; }
                if (c0 + 1 >= cntb) { sacc[ni][1] = -1e30f; sacc[ni][3] = -1e30f; }
            }
        }

        // fixed-max softmax (bias 0)
        float rs0 = 0.f, rs1 = 0.f;
#pragma unroll
        for (int ni = 0; ni < 8; ni++) {
            sacc[ni][0] = exp2q(sacc[ni][0]); rs0 += sacc[ni][0];
            sacc[ni][1] = exp2q(sacc[ni][1]); rs0 += sacc[ni][1];
            sacc[ni][2] = exp2q(sacc[ni][2]); rs1 += sacc[ni][2];
            sacc[ni][3] = exp2q(sacc[ni][3]); rs1 += sacc[ni][3];
        }
        rs0 += __shfl_xor_sync(0xffffffffu, rs0, 1);
        rs0 += __shfl_xor_sync(0xffffffffu, rs0, 2);
        rs1 += __shfl_xor_sync(0xffffffffu, rs1, 1);
        rs1 += __shfl_xor_sync(0xffffffffu, rs1, 2);
        l0 += rs0;
        l1 += rs1;

        uint32_t pah[4][4];
#pragma unroll
        for (int j = 0; j < 4; j++) {
            pah[j][0] = packh2(sacc[2 * j][0], sacc[2 * j][1]);
            pah[j][1] = packh2(sacc[2 * j][2], sacc[2 * j][3]);
            pah[j][2] = packh2(sacc[2 * j + 1][0], sacc[2 * j + 1][1]);
            pah[j][3] = packh2(sacc[2 * j + 1][2], sacc[2 * j + 1][3]);
        }

        // O += P V : 1 pass
#pragma unroll
        for (int j = 0; j < 4; j++) {
            uint32_t rowoff = (uint32_t)((16 * j + (lane & 15)) * 144);
#pragma unroll
            for (int n2 = 0; n2 < 8; n2 += 2) {
                uint32_t va = vbase + rowoff + n2 * 16 + ((lane >> 4) & 1) * 16;
                uint32_t vrh[4];
                ldmx4_trans(vrh, va);
                mma_f16(oacc[n2],     pah[j], &vrh[0]);
                mma_f16(oacc[n2 + 1], pah[j], &vrh[2]);
            }
        }
        __syncthreads();
    }

    float inv0 = 1.0f / l0, inv1 = 1.0f / l1;
    const size_t row0 = qrow + g;
#pragma unroll
    for (int ni = 0; ni < 8; ni++) {
        size_t cp = (size_t)(h * 32 + ni * 4 + tq);
        float x0 = oacc[ni][0] * inv0, y0 = oacc[ni][1] * inv0;
        float x1 = oacc[ni][2] * inv1, y1 = oacc[ni][3] * inv1;
        g_X[row0 * 512 + cp]       = packh2(x0, y0);
        g_X[(row0 + 8) * 512 + cp] = packh2(x1, y1);
    }
}

// ============================ Launch ============================
extern "C" void kernel_launch(void* const* d_in, const int* in_sizes, int n_in,
                              void* d_out, int out_size)
{
    const float*        enc      = (const float*)d_in[0];
    const unsigned int* enc_mask = (const unsigned int*)d_in[1];
    const float*        dec      = (const float*)d_in[2];
    const float*        q_w      = (const float*)d_in[3];
    const float*        q_b      = (const float*)d_in[4];
    const float*        k_w      = (const float*)d_in[5];
    const float*        k_b      = (const float*)d_in[6];
    const float*        v_w      = (const float*)d_in[7];
    const float*        v_b      = (const float*)d_in[8];
    const float*        o_w      = (const float*)d_in[9];
    const float*        o_b      = (const float*)d_in[10];
    float*              out      = (float*)d_out;

    uint32_t *pdec, *penc, *pwt, *pQ, *pK, *pV, *pX;
    cudaGetSymbolAddress((void**)&pdec, g_dec);
    cudaGetSymbolAddress((void**)&penc, g_enc);
    cudaGetSymbolAddress((void**)&pwt,  g_wt);
    cudaGetSymbolAddress((void**)&pQ,   g_Q);
    cudaGetSymbolAddress((void**)&pK,   g_K);
    cudaGetSymbolAddress((void**)&pV,   g_V);
    cudaGetSymbolAddress((void**)&pX,   g_X);

    cudaFuncSetAttribute(hgemm_qkv, cudaFuncAttributeMaxDynamicSharedMemorySize, 2 * GST);
    cudaFuncSetAttribute(hgemm_o,   cudaFuncAttributeMaxDynamicSharedMemorySize, 2 * GST);
    cudaFuncSetAttribute(attn_mma,  cudaFuncAttributeMaxDynamicSharedMemorySize, ATTN_SMEM);

    conv_wt_all<<<dim3(32, 16, 4), 256>>>(q_w, k_w, v_w, o_w, pwt);
    scan_mask<<<BB, 1024>>>(enc_mask);
    conv_acts<<<(4096 + 8192) * 256 / 256, 256>>>(dec, enc, pdec, penc);

    hgemm_qkv<<<dim3(8, 160), 256, 2 * GST>>>(pdec, penc, pwt,
                                              q_b, k_b, v_b, pQ, pK, pV);

    attn_mma<<<dim3(SDEC / 64, NH, BB), 128, ATTN_SMEM>>>();

    hgemm_o<<<dim3(8, 32), 256, 2 * GST>>>(pX, pwt + 3 * WSZ, o_b, out);
}